// round 6
// baseline (speedup 1.0000x reference)
#include <cuda_runtime.h>
#include <cuda_bf16.h>

// Problem constants
#define BATCH 8
#define NN    4096        // nodes per batch (64*64 spatial)
#define CC    64          // channels
#define KOUT  8           // neighbors kept
#define KTOP  9           // k+1 (self included, dropped at emit)

#define NODES_ELEMS (BATCH * NN * CC)          // 2,097,152 floats
#define EDGE_PER_B  (2 * NN * KOUT)            // 65,536 floats per batch

// Tiling for the distance kernel
#define TI 64
#define TJ 64
#define PAD 68            // padded row stride (floats), 16B-aligned rows
#define THREADS 256

__device__ float g_xx[BATCH * NN];             // per-node squared norm

// monotonic float -> uint mapping (ascending float == ascending uint)
__device__ __forceinline__ unsigned int fkey(float f) {
    unsigned int u = __float_as_uint(f);
    return u ^ ((u >> 31) ? 0xFFFFFFFFu : 0x80000000u);
}

// ---------------------------------------------------------------------------
// Kernel A: projection  nodes[b][n][o] = sum_c feat[b][c][n] * W[o][c] + bias[o]
// also computes xx[b][n] = sum_o nodes^2
// ---------------------------------------------------------------------------
__global__ __launch_bounds__(256)
void proj_kernel(const float* __restrict__ feat,
                 const float* __restrict__ W,
                 const float* __restrict__ bias,
                 float* __restrict__ nodes_out) {
    __shared__ float Wsm[CC * CC];   // [c][o]
    __shared__ float bsm[CC];
    int tid = threadIdx.x;
    for (int idx = tid; idx < CC * CC; idx += blockDim.x) {
        int o = idx & 63, c = idx >> 6;
        Wsm[c * CC + o] = W[o * CC + c];
    }
    if (tid < CC) bsm[tid] = bias[tid];
    __syncthreads();

    int ng = blockIdx.x * blockDim.x + tid;   // 0 .. BATCH*NN-1
    int b = ng >> 12;
    int n = ng & (NN - 1);
    const float* f = feat + (size_t)b * CC * NN + n;

    float acc[CC];
#pragma unroll
    for (int o = 0; o < CC; o++) acc[o] = bsm[o];

    for (int c = 0; c < CC; c++) {
        float fv = f[(size_t)c * NN];
#pragma unroll
        for (int o = 0; o < CC; o++) acc[o] = fmaf(fv, Wsm[c * CC + o], acc[o]);
    }

    float xx = 0.f;
#pragma unroll
    for (int o = 0; o < CC; o++) xx = fmaf(acc[o], acc[o], xx);
    g_xx[ng] = xx;

    float4* dst = (float4*)(nodes_out + (size_t)ng * CC);
#pragma unroll
    for (int o = 0; o < CC / 4; o++)
        dst[o] = make_float4(acc[4 * o], acc[4 * o + 1], acc[4 * o + 2], acc[4 * o + 3]);
}

// ---------------------------------------------------------------------------
// Kernel B: fused distance GEMM + top-9 per row + edge emission
// Grid: (NN/TI, BATCH), block: 256 threads
// smem (static, < 48KB): XiT[64][68] | XjT[64][68] (dt aliases XjT) | xxi | xxj
// dt (distance tile) reuses XjT's storage: all reads of XjT happen in the FMA
// phase, a __syncthreads separates them from the dt writes.
// ---------------------------------------------------------------------------
__global__ __launch_bounds__(THREADS)
void knn_kernel(const float* __restrict__ nodes, float* __restrict__ edges) {
    __shared__ float XiT[CC * PAD];        // [c][i]  c*PAD + i
    __shared__ float XjT[CC * PAD];        // [c][j], later reused as dt[i][j]
    __shared__ float xxi[TI];
    __shared__ float xxj[TJ];
    float* dt = XjT;                       // alias — disjoint lifetime

    int tid = threadIdx.x;
    int b   = blockIdx.y;
    int i0  = blockIdx.x * TI;
    const float* nodesB = nodes + (size_t)b * NN * CC;

    // load Xi tile (transposed) + xxi
    for (int idx = tid; idx < TI * CC; idx += THREADS) {
        int r = idx >> 6, c = idx & 63;
        XiT[c * PAD + r] = nodesB[(size_t)(i0 + r) * CC + c];
    }
    if (tid < TI) xxi[tid] = g_xx[b * NN + i0 + tid];

    int ty = tid >> 4, tx = tid & 15;      // compute-phase 16x16 thread tile
    int srow  = tid >> 2;                  // scan-phase: 4 scanners per row
    int spart = tid & 3;

    unsigned long long heap[KTOP];
#pragma unroll
    for (int q = 0; q < KTOP; q++) heap[q] = 0xFFFFFFFFFFFFFFFFull;

    __syncthreads();

    for (int jt = 0; jt < NN / TJ; jt++) {
        // load Xj tile (transposed) + xxj
        for (int idx = tid; idx < TJ * CC; idx += THREADS) {
            int r = idx >> 6, c = idx & 63;
            XjT[c * PAD + r] = nodesB[(size_t)(jt * TJ + r) * CC + c];
        }
        if (tid < TJ) xxj[tid] = g_xx[b * NN + jt * TJ + tid];
        __syncthreads();

        // 4x4 register micro-tile dot products over c = 0..63
        float acc[4][4];
#pragma unroll
        for (int a = 0; a < 4; a++)
#pragma unroll
            for (int q = 0; q < 4; q++) acc[a][q] = 0.f;

#pragma unroll 4
        for (int c = 0; c < CC; c++) {
            float4 av = *(const float4*)&XiT[c * PAD + 4 * ty];
            float4 bv = *(const float4*)&XjT[c * PAD + 4 * tx];
            float aa[4] = {av.x, av.y, av.z, av.w};
            float bb[4] = {bv.x, bv.y, bv.z, bv.w};
#pragma unroll
            for (int a = 0; a < 4; a++)
#pragma unroll
                for (int q = 0; q < 4; q++)
                    acc[a][q] = fmaf(aa[a], bb[q], acc[a][q]);
        }

        // all XjT reads done — safe to overwrite the aliased dt region
        __syncthreads();

        // distances -> smem tile (dt aliases XjT)
#pragma unroll
        for (int a = 0; a < 4; a++) {
            float xi2 = xxi[4 * ty + a];
            float4 dv;
            dv.x = xi2 - 2.0f * acc[a][0] + xxj[4 * tx + 0];
            dv.y = xi2 - 2.0f * acc[a][1] + xxj[4 * tx + 1];
            dv.z = xi2 - 2.0f * acc[a][2] + xxj[4 * tx + 2];
            dv.w = xi2 - 2.0f * acc[a][3] + xxj[4 * tx + 3];
            *(float4*)&dt[(4 * ty + a) * PAD + 4 * tx] = dv;
        }
        __syncthreads();

        // scan: each of 4 threads per row handles 16 strided candidates
        int jbase = jt * TJ;
#pragma unroll
        for (int s = 0; s < 16; s++) {
            int jl = spart + 4 * s;
            float d = dt[srow * PAD + jl];
            unsigned long long key =
                ((unsigned long long)fkey(d) << 32) | (unsigned int)(jbase + jl);
            if (key < heap[KTOP - 1]) {
                heap[KTOP - 1] = key;
#pragma unroll
                for (int q = KTOP - 1; q > 0; q--) {
                    if (heap[q] < heap[q - 1]) {
                        unsigned long long t = heap[q];
                        heap[q] = heap[q - 1];
                        heap[q - 1] = t;
                    }
                }
            }
        }
        __syncthreads();
    }

    // final merge across the 4 scanner lanes of each row (branch-free shfl min)
    float* esrc = edges + (size_t)b * EDGE_PER_B;
    float* eidx = esrc + NN * KOUT;
    int il = i0 + srow;                    // local node index within batch
    unsigned long long prev = 0;

    for (int r = 0; r < KTOP; r++) {
        unsigned long long cand = 0xFFFFFFFFFFFFFFFFull;
#pragma unroll
        for (int q = 0; q < KTOP; q++) {
            unsigned long long h = heap[q];
            if (h > prev && h < cand) cand = h;
        }
        unsigned long long m = cand;
        unsigned long long o1 = __shfl_xor_sync(0xFFFFFFFFu, m, 1, 4);
        if (o1 < m) m = o1;
        unsigned long long o2 = __shfl_xor_sync(0xFFFFFFFFu, m, 2, 4);
        if (o2 < m) m = o2;
        prev = m;
        if (r >= 1 && spart == 0) {
            int nb = (int)(m & 0xFFFFFFFFull);
            esrc[(size_t)il * KOUT + (r - 1)] = (float)il;
            eidx[(size_t)il * KOUT + (r - 1)] = (float)nb;
        }
    }
}

// ---------------------------------------------------------------------------
// Launch
// ---------------------------------------------------------------------------
extern "C" void kernel_launch(void* const* d_in, const int* in_sizes, int n_in,
                              void* d_out, int out_size) {
    const float* feat = (const float*)d_in[0];   // features (8,64,64,64)
    const float* W    = (const float*)d_in[1];   // proj_w (64,64)
    const float* bias = (const float*)d_in[2];   // proj_b (64,)
    // d_in[3] = k (compile-time 8)
    float* out = (float*)d_out;

    proj_kernel<<<(BATCH * NN) / 256, 256>>>(feat, W, bias, out);

    dim3 grid(NN / TI, BATCH);
    knn_kernel<<<grid, THREADS>>>(out, out + NODES_ELEMS);
}